// round 9
// baseline (speedup 1.0000x reference)
#include <cuda_runtime.h>
#include <cuda_bf16.h>
#include <math.h>
#include <stdint.h>

#define B_TOK   4096
#define DM      1024
#define DH      2048
#define N_TILES 8

typedef __nv_bfloat16 bf16;

// ---------------- scratch (device globals; no allocation allowed) -----------
__device__ bf16  g_xhi [B_TOK * DM];
__device__ bf16  g_xlo [B_TOK * DM];
__device__ float g_Hr  [B_TOK * DM];
__device__ bf16  g_H2hi[B_TOK * DH];
__device__ bf16  g_H2lo[B_TOK * DH];
__device__ bf16  g_selhi[B_TOK * DM];
__device__ bf16  g_sello[B_TOK * DM];
__device__ int   g_tile[B_TOK];
__device__ int   g_perm[B_TOK];
__device__ int   g_cnt[N_TILES];
__device__ int   g_off[N_TILES];
__device__ int   g_cur[N_TILES];

// ---------------- helpers ----------------------------------------------------
__device__ __forceinline__ uint32_t smem_u32(const void* p) {
    uint32_t a;
    asm("{ .reg .u64 t; cvta.to.shared.u64 t, %1; cvt.u32.u64 %0, t; }"
        : "=r"(a) : "l"(p));
    return a;
}
__device__ __forceinline__ void cp_async16(uint32_t dst, const void* src) {
    asm volatile("cp.async.cg.shared.global [%0], [%1], 16;"
                 :: "r"(dst), "l"(src) : "memory");
}
__device__ __forceinline__ void cp_commit() {
    asm volatile("cp.async.commit_group;" ::: "memory");
}
__device__ __forceinline__ void cp_wait1() {
    asm volatile("cp.async.wait_group 1;" ::: "memory");
}
__device__ __forceinline__ void ldsm_x4(uint32_t* r, uint32_t addr) {
    asm volatile("ldmatrix.sync.aligned.m8n8.x4.shared.b16 {%0,%1,%2,%3}, [%4];"
                 : "=r"(r[0]), "=r"(r[1]), "=r"(r[2]), "=r"(r[3]) : "r"(addr));
}
__device__ __forceinline__ void ldsm_x4_t(uint32_t* r, uint32_t addr) {
    asm volatile("ldmatrix.sync.aligned.m8n8.x4.trans.shared.b16 {%0,%1,%2,%3}, [%4];"
                 : "=r"(r[0]), "=r"(r[1]), "=r"(r[2]), "=r"(r[3]) : "r"(addr));
}
__device__ __forceinline__ void mma16816(float* c, const uint32_t* a, const uint32_t* b) {
    asm volatile("mma.sync.aligned.m16n8k16.row.col.f32.bf16.bf16.f32 "
                 "{%0,%1,%2,%3}, {%4,%5,%6,%7}, {%8,%9}, {%0,%1,%2,%3};"
                 : "+f"(c[0]), "+f"(c[1]), "+f"(c[2]), "+f"(c[3])
                 : "r"(a[0]), "r"(a[1]), "r"(a[2]), "r"(a[3]),
                   "r"(b[0]), "r"(b[1]));
}
__device__ __forceinline__ float gelu_exact(float v) {
    return 0.5f * v * (1.0f + erff(v * 0.70710678118654752440f));
}
__device__ __forceinline__ uint32_t pack_hi2(float a, float b) {
    __nv_bfloat162 p(__float2bfloat16(a), __float2bfloat16(b));
    return *(uint32_t*)&p;
}
__device__ __forceinline__ uint32_t pack_lo2(float a, float b, uint32_t hi) {
    __nv_bfloat162 h = *(__nv_bfloat162*)&hi;
    __nv_bfloat162 p(__float2bfloat16(a - __bfloat162float(h.x)),
                     __float2bfloat16(b - __bfloat162float(h.y)));
    return *(uint32_t*)&p;
}

// ---------------- small kernels ---------------------------------------------
__global__ void zero_kernel() {
    int i = threadIdx.x;
    if (i < N_TILES) { g_cnt[i] = 0; g_cur[i] = 0; }
}

__global__ void split_acts_kernel(const float* __restrict__ src,
                                  bf16* __restrict__ xhi, bf16* __restrict__ xlo) {
    int i = blockIdx.x * blockDim.x + threadIdx.x;   // float4 index
    const float4 v = ((const float4*)src)[i];
    uint32_t h0 = pack_hi2(v.x, v.y), h1 = pack_hi2(v.z, v.w);
    uint32_t l0 = pack_lo2(v.x, v.y, h0), l1 = pack_lo2(v.z, v.w, h1);
    ((uint2*)xhi)[i] = make_uint2(h0, h1);
    ((uint2*)xlo)[i] = make_uint2(l0, l1);
}

// ---------------- router logits + argmax ------------------------------------
__global__ __launch_bounds__(256) void router_argmax_kernel(
    const float* __restrict__ Hr, const float* __restrict__ Wr2,
    const float* __restrict__ br2,
    float* __restrict__ out_logits, float* __restrict__ out_idx)
{
    const int token = blockIdx.x * 8 + (threadIdx.x >> 5);
    const int lane  = threadIdx.x & 31;
    const float* h  = Hr + (size_t)token * DM;

    float acc[N_TILES];
#pragma unroll
    for (int n = 0; n < N_TILES; n++) acc[n] = 0.f;
    for (int k = lane; k < DM; k += 32) {
        float hv = h[k];
        float4 w0 = *(const float4*)(Wr2 + (size_t)k * N_TILES);
        float4 w1 = *(const float4*)(Wr2 + (size_t)k * N_TILES + 4);
        acc[0] = fmaf(hv, w0.x, acc[0]); acc[1] = fmaf(hv, w0.y, acc[1]);
        acc[2] = fmaf(hv, w0.z, acc[2]); acc[3] = fmaf(hv, w0.w, acc[3]);
        acc[4] = fmaf(hv, w1.x, acc[4]); acc[5] = fmaf(hv, w1.y, acc[5]);
        acc[6] = fmaf(hv, w1.z, acc[6]); acc[7] = fmaf(hv, w1.w, acc[7]);
    }
#pragma unroll
    for (int n = 0; n < N_TILES; n++)
#pragma unroll
        for (int s = 16; s > 0; s >>= 1)
            acc[n] += __shfl_xor_sync(0xFFFFFFFFu, acc[n], s);
    if (lane == 0) {
        float best = -1e30f; int bi = 0;
#pragma unroll
        for (int n = 0; n < N_TILES; n++) {
            float l = (acc[n] + br2[n]) * 2.0f;
            if (out_logits) out_logits[(size_t)token * N_TILES + n] = l;
            if (l > best) { best = l; bi = n; }
        }
        g_tile[token] = bi;
        atomicAdd(&g_cnt[bi], 1);
        if (out_idx) out_idx[token] = (float)bi;
    }
}

__global__ void offsets_kernel() {
    if (threadIdx.x == 0) {
        int s = 0;
        for (int t = 0; t < N_TILES; t++) { g_off[t] = s; s += g_cnt[t]; }
    }
}

__global__ void scatter_kernel() {
    int i = blockIdx.x * blockDim.x + threadIdx.x;
    if (i < B_TOK) {
        int t = g_tile[i];
        int pos = g_off[t] + atomicAdd(&g_cur[t], 1);
        g_perm[pos] = i;
    }
}

// ---------------- HMMA bf16x3 GEMM, fused fp32-weight conversion -------------
// C[M,N] = act(A[M,K] @ W[K,N] + b).
// A: hi/lo bf16 row-major, via 3-stage cp.async.
// W: fp32 [K][N] directly from input; loader converts to hi/lo bf16 in-reg,
// STS K-major tiles, B fragments via ldmatrix.x4.trans.
// bf16x3: hi*hi + hi*lo + lo*hi, fp32 accumulation.
// Block 128x128, 256 threads, 8 warps (2Mx4N), warp tile 64x32, BK=16.
// 3 stages x 16KB = 48KB static smem. __launch_bounds__(256,2): 2 CTAs/SM
// so one CTA's HMMA stream covers the other's barrier/cp.wait bubbles.

#define BK       16
#define AROWB    32                     // A row bytes (BK bf16)
#define BROWB    256                    // B row bytes (128 bf16)
#define SOFF_AHI 0
#define SOFF_ALO 4096
#define SOFF_BHI 8192
#define SOFF_BLO 12288
#define STAGE_B  16384
#define NSTAGE   3

template<int MODE, bool ACT, bool F32OUT>
__global__ void __launch_bounds__(256, 2) hgemm_kernel(
    const bf16* __restrict__ Ahi, const bf16* __restrict__ Alo,
    const float* __restrict__ Wf,
    const float* __restrict__ bg,
    float* __restrict__ Cf, bf16* __restrict__ Chi, bf16* __restrict__ Clo,
    int N, int K, int M0)
{
    const int tile = (MODE == 0) ? 0 : blockIdx.z;
    int Mvalid, moff;
    if (MODE == 0) { Mvalid = M0;          moff = 0; }
    else           { Mvalid = g_cnt[tile]; moff = g_off[tile]; }

    const int mstart = blockIdx.y * 128;
    if (mstart >= Mvalid) return;
    const int nstart = blockIdx.x * 128;

    __shared__ __align__(128) char smem[NSTAGE * STAGE_B];
    const uint32_t sb = smem_u32(smem);
    const int tid  = threadIdx.x;
    const int wid  = tid >> 5;
    const int lane = tid & 31;
    const int warp_m = (wid & 1) * 64;
    const int warp_n = (wid >> 1) * 32;
    const int g     = lane >> 2;
    const int tig   = lane & 3;
    const int matid = lane >> 3;
    const int mrow8 = lane & 7;

    // ---- A loader (cp.async): one row per thread-pair, 16B chunk tid&1 ----
    const int lrow = tid >> 1;
    const int kc   = tid & 1;
    const int keo  = kc * 8;
    int mg = mstart + lrow; if (mg > Mvalid - 1) mg = Mvalid - 1;
    size_t aidx;
    if (MODE == 0)      aidx = (size_t)mg;
    else if (MODE == 1) aidx = (size_t)g_perm[moff + mg];
    else                aidx = (size_t)(moff + mg);
    const bf16* gah = Ahi + aidx * (size_t)K;
    const bf16* gal = Alo + aidx * (size_t)K;
    const uint32_t astoff = (uint32_t)lrow * AROWB + (uint32_t)kc * 16;

    // ---- B loader (LDG fp32 + cvt + STS): row tid>>4, 8-float seg tid&15 ----
    const int brow = tid >> 4;            // 0..15 (k within block)
    const int bseg = tid & 15;            // 8-float segment
    const float* gbf = Wf + (size_t)tile * (size_t)K * (size_t)N
                          + (size_t)nstart + (size_t)bseg * 8;
    const uint32_t bstoff = (uint32_t)brow * BROWB
                          + (uint32_t)(((bseg >> 1) ^ (brow & 7)) * 32)
                          + (uint32_t)((bseg & 1) * 16);

    // ---- ldmatrix addresses ----
    const uint32_t a_ls = (uint32_t)(warp_m + (matid & 1) * 8 + mrow8) * AROWB
                        + (uint32_t)(matid >> 1) * 16;
    const uint32_t bt_row = (uint32_t)((matid & 1) * 8 + mrow8) * BROWB
                          + (uint32_t)(matid >> 1) * 16;
    const uint32_t bt_c0 = (uint32_t)((((warp_n >> 4) + 0) ^ mrow8) * 32);
    const uint32_t bt_c1 = (uint32_t)((((warp_n >> 4) + 1) ^ mrow8) * 32);

    const int nk = K / BK;

    // B register stage (fp32, next block)
    float4 bf0, bf1;

    // ---- prologue ----
#pragma unroll
    for (int s = 0; s < 2; s++) {
        const uint32_t buf = sb + s * STAGE_B;
        cp_async16(buf + SOFF_AHI + astoff, gah + s * BK + keo);
        cp_async16(buf + SOFF_ALO + astoff, gal + s * BK + keo);
        cp_commit();
    }
    {
        const float* p = gbf + (size_t)brow * N;
        bf0 = *(const float4*)(p);
        bf1 = *(const float4*)(p + 4);
        uint32_t h0 = pack_hi2(bf0.x, bf0.y), h1 = pack_hi2(bf0.z, bf0.w);
        uint32_t h2 = pack_hi2(bf1.x, bf1.y), h3 = pack_hi2(bf1.z, bf1.w);
        uint32_t l0 = pack_lo2(bf0.x, bf0.y, h0), l1 = pack_lo2(bf0.z, bf0.w, h1);
        uint32_t l2 = pack_lo2(bf1.x, bf1.y, h2), l3 = pack_lo2(bf1.z, bf1.w, h3);
        *(uint4*)(smem + SOFF_BHI + bstoff) = make_uint4(h0, h1, h2, h3);
        *(uint4*)(smem + SOFF_BLO + bstoff) = make_uint4(l0, l1, l2, l3);
        if (nk > 1) {
            const float* q = gbf + (size_t)(BK + brow) * N;
            bf0 = *(const float4*)(q);
            bf1 = *(const float4*)(q + 4);
        }
    }

    float acc[4][4][4];
#pragma unroll
    for (int i = 0; i < 4; i++)
#pragma unroll
        for (int j = 0; j < 4; j++)
#pragma unroll
            for (int c = 0; c < 4; c++) acc[i][j][c] = 0.f;

    int sc = 0;   // stage of kt
    int sp = 2;   // stage of kt+2
    for (int kt = 0; kt < nk; kt++) {
        cp_wait1();
        __syncthreads();

        // A(kt+2) via cp.async into stage sp
        if (kt + 2 < nk) {
            const uint32_t buf = sb + sp * STAGE_B;
            const int k0 = (kt + 2) * BK;
            cp_async16(buf + SOFF_AHI + astoff, gah + k0 + keo);
            cp_async16(buf + SOFF_ALO + astoff, gal + k0 + keo);
        }
        cp_commit();

        // B(kt+1): convert regs -> STS into stage (kt+1)%3
        if (kt + 1 < nk) {
            char* buf = smem + ((sc + 1) % NSTAGE) * STAGE_B;
            uint32_t h0 = pack_hi2(bf0.x, bf0.y), h1 = pack_hi2(bf0.z, bf0.w);
            uint32_t h2 = pack_hi2(bf1.x, bf1.y), h3 = pack_hi2(bf1.z, bf1.w);
            uint32_t l0 = pack_lo2(bf0.x, bf0.y, h0), l1 = pack_lo2(bf0.z, bf0.w, h1);
            uint32_t l2 = pack_lo2(bf1.x, bf1.y, h2), l3 = pack_lo2(bf1.z, bf1.w, h3);
            *(uint4*)(buf + SOFF_BHI + bstoff) = make_uint4(h0, h1, h2, h3);
            *(uint4*)(buf + SOFF_BLO + bstoff) = make_uint4(l0, l1, l2, l3);
        }
        // B(kt+2) -> regs
        if (kt + 2 < nk) {
            const float* q = gbf + (size_t)((kt + 2) * BK + brow) * N;
            bf0 = *(const float4*)(q);
            bf1 = *(const float4*)(q + 4);
        }

        const uint32_t st = sb + sc * STAGE_B;

        // B fragments via ldmatrix.trans: 2 x4 per hi/lo cover 4 n-tiles
        uint32_t Bh[8], Bl[8];
        ldsm_x4_t(&Bh[0], st + SOFF_BHI + bt_row + bt_c0);
        ldsm_x4_t(&Bh[4], st + SOFF_BHI + bt_row + bt_c1);
        ldsm_x4_t(&Bl[0], st + SOFF_BLO + bt_row + bt_c0);
        ldsm_x4_t(&Bl[4], st + SOFF_BLO + bt_row + bt_c1);

#pragma unroll
        for (int mt = 0; mt < 4; mt++) {
            const uint32_t aa = st + a_ls + (uint32_t)mt * 16 * AROWB;
            uint32_t Ah[4], Al[4];
            ldsm_x4(Ah, aa + SOFF_AHI);
            ldsm_x4(Al, aa + SOFF_ALO);
#pragma unroll
            for (int nt = 0; nt < 4; nt++) {
                const uint32_t* bh = &Bh[(nt >> 1) * 4 + (nt & 1) * 2];
                const uint32_t* bl = &Bl[(nt >> 1) * 4 + (nt & 1) * 2];
                mma16816(acc[mt][nt], Ah, bh);
                mma16816(acc[mt][nt], Ah, bl);
                mma16816(acc[mt][nt], Al, bh);
            }
        }

        sc = (sc == NSTAGE - 1) ? 0 : sc + 1;
        sp = (sp == NSTAGE - 1) ? 0 : sp + 1;
    }

    // ---- epilogue ----
    const float* bias = bg + (size_t)tile * N;
#pragma unroll
    for (int mt = 0; mt < 4; mt++) {
#pragma unroll
        for (int half = 0; half < 2; half++) {
            const int m = mstart + warp_m + mt * 16 + g + half * 8;
            if (m >= Mvalid) continue;
            size_t orow;
            if (MODE == 0)      orow = (size_t)m;
            else if (MODE == 1) orow = (size_t)(moff + m);
            else                orow = (size_t)g_perm[moff + m];
#pragma unroll
            for (int nt = 0; nt < 4; nt++) {
                const int n = nstart + warp_n + nt * 8 + tig * 2;
                float v0 = acc[mt][nt][half * 2 + 0] + bias[n + 0];
                float v1 = acc[mt][nt][half * 2 + 1] + bias[n + 1];
                if (ACT) { v0 = gelu_exact(v0); v1 = gelu_exact(v1); }
                if (F32OUT) {
                    *(float2*)(Cf + orow * (size_t)N + n) = make_float2(v0, v1);
                } else {
                    uint32_t h = pack_hi2(v0, v1);
                    uint32_t l = pack_lo2(v0, v1, h);
                    *(uint32_t*)(Chi + orow * (size_t)N + n) = h;
                    *(uint32_t*)(Clo + orow * (size_t)N + n) = l;
                }
            }
        }
    }
}

// ---------------- launch -----------------------------------------------------
// __device__ globals passed as kernel args MUST be resolved through
// cudaGetSymbolAddress (host shadow vs device copy under ATS on GB300).
#define SYMADDR(T, var, sym) \
    T* var; { void* _p; cudaGetSymbolAddress(&_p, sym); var = (T*)_p; }

extern "C" void kernel_launch(void* const* d_in, const int* in_sizes, int n_in,
                              void* d_out, int out_size)
{
    const float* x   = (const float*)d_in[0];
    const float* Wr1 = (const float*)d_in[1];
    const float* br1 = (const float*)d_in[2];
    const float* Wr2 = (const float*)d_in[3];
    const float* br2 = (const float*)d_in[4];
    const float* W1  = (const float*)d_in[5];
    const float* b1  = (const float*)d_in[6];
    const float* W2  = (const float*)d_in[7];
    const float* b2  = (const float*)d_in[8];
    const float* Wo  = (const float*)d_in[9];
    const float* bo  = (const float*)d_in[10];

    SYMADDR(bf16,  xhi,   g_xhi);   SYMADDR(bf16,  xlo,   g_xlo);
    SYMADDR(float, Hr,    g_Hr);
    SYMADDR(bf16,  H2hi,  g_H2hi);  SYMADDR(bf16,  H2lo,  g_H2lo);
    SYMADDR(bf16,  selhi, g_selhi); SYMADDR(bf16,  sello, g_sello);

    float* out = (float*)d_out;
    float* out_main   = out;
    float* out_idx    = nullptr;
    float* out_logits = nullptr;
    const long long need_all = (long long)B_TOK * DM + B_TOK + (long long)B_TOK * N_TILES;
    if ((long long)out_size >= need_all) {
        out_idx    = out + (size_t)B_TOK * DM;
        out_logits = out + (size_t)B_TOK * DM + B_TOK;
    } else if ((long long)out_size >= (long long)B_TOK * DM + B_TOK) {
        out_idx = out + (size_t)B_TOK * DM;
    }

    // 1) counters + activation split
    zero_kernel<<<1, 32>>>();
    split_acts_kernel<<<(B_TOK * DM / 4) / 256, 256>>>(x, xhi, xlo);

    // 2) router hidden: Hr = gelu(x @ Wr1 + br1)  (fp32 out)
    hgemm_kernel<0, true, true><<<dim3(DM / 128, B_TOK / 128), 256>>>(
        xhi, xlo, Wr1, br1, Hr, nullptr, nullptr, DM, DM, B_TOK);

    // 3) logits + argmax + counts; 4) offsets + scatter
    router_argmax_kernel<<<B_TOK / 8, 256>>>(Hr, Wr2, br2, out_logits, out_idx);
    offsets_kernel<<<1, 1>>>();
    scatter_kernel<<<B_TOK / 256, 256>>>();

    // 5) tile MLP layer 1: gather x rows, gelu, hi/lo out (compact order)
    hgemm_kernel<1, true, false><<<dim3(DH / 128, B_TOK / 128, N_TILES), 256>>>(
        xhi, xlo, W1, b1, nullptr, H2hi, H2lo, DH, DM, 0);

    // 6) tile MLP layer 2: compact in, scatter out, hi/lo
    hgemm_kernel<2, false, false><<<dim3(DM / 128, B_TOK / 128, N_TILES), 256>>>(
        H2hi, H2lo, W2, b2, nullptr, selhi, sello, DM, DH, 0);

    // 7) output projection (fp32 out to d_out)
    hgemm_kernel<0, false, true><<<dim3(DM / 128, B_TOK / 128), 256>>>(
        selhi, sello, Wo, bo, out_main, nullptr, nullptr, DM, DM, B_TOK);
}